// round 16
// baseline (speedup 1.0000x reference)
#include <cuda_runtime.h>
#include <cstdint>

#define H 128
#define DI 64
#define MAX_N 50000
#define MAX_M 20000
#define MAX_E 1000000
#define SCAN_B 512

// ---------------- scratch (no allocations allowed) ----------------
__device__ float  g_pmsg[MAX_M * H];
__device__ float  g_imsg[MAX_N * H];
__device__ int    g_i32[MAX_E];
__device__ int    g_p32[MAX_E];
__device__ int    g_psrc[MAX_E];
__device__ int    g_isrc[MAX_E];
__device__ int    g_prow[MAX_M + 1];
__device__ int    g_irow[MAX_N + 1];
__device__ int    g_pcur[MAX_M];
__device__ int    g_icur[MAX_N];
__device__ int    g_pcnt[MAX_M];
__device__ int    g_icnt[MAX_N];
__device__ int    g_pbsum[(MAX_M + SCAN_B - 1) / SCAN_B];
__device__ int    g_ibsum[(MAX_N + SCAN_B - 1) / SCAN_B];
__device__ unsigned g_barcnt;

// ---------------- barrier reset (launch idx 0 each call) ----------------
__global__ void reset_kernel() { g_barcnt = 0u; }

// ---------------- software grid barrier (all blocks co-resident) ----------------
__device__ __forceinline__ void gbar(unsigned target) {
    __syncthreads();
    if (threadIdx.x == 0) {
        __threadfence();
        atomicAdd(&g_barcnt, 1u);
        while (atomicAdd(&g_barcnt, 0u) < target) { }
        __threadfence();
    }
    __syncthreads();
}

// ---------------- persistent CSR build: zero -> count -> reduce -> scan -> scanc -> place ----------------
// grid = pblocks + iblocks (= 138 full-size) blocks of SCAN_B threads; all co-resident.
__global__ __launch_bounds__(SCAN_B)
void csr_kernel(const void* __restrict__ iraw, const void* __restrict__ praw,
                int E, int M_, int N_, int pblocks, int iblocks, int nb) {
    __shared__ int sh[SCAN_B];
    const int b = blockIdx.x;
    const int t = threadIdx.x;
    const int nthr = nb * SCAN_B;
    const int gt = b * SCAN_B + t;

    // is64 detect (every block samples the SAME first words -> identical verdict)
    __shared__ int s_is64;
    if (t < 32) {
        int nsamp = (E / 2 < 64) ? E / 2 : 64;
        unsigned long long hi = 0;
        for (int i = t; i < nsamp; i += 32)
            hi |= (((const unsigned long long*)iraw)[i] >> 32);
        unsigned any = __ballot_sync(0xFFFFFFFFu, hi != 0ULL);
        if (t == 0) s_is64 = (any == 0u) ? 1 : 0;
    }
    __syncthreads();
    const int is64 = s_is64;

    // Phase Z: zero both count arrays
    for (int i = gt; i < N_; i += nthr) g_icnt[i] = 0;
    for (int i = gt; i < M_; i += nthr) g_pcnt[i] = 0;
    gbar(1u * nb);

    // Phase C: count + narrow
    for (int e = gt; e < E; e += nthr) {
        int s = is64 ? (int)((const long long*)iraw)[e] : ((const int*)iraw)[e];
        int d = is64 ? (int)((const long long*)praw)[e] : ((const int*)praw)[e];
        g_i32[e] = s;
        g_p32[e] = d;
        atomicAdd(&g_icnt[s], 1);
        atomicAdd(&g_pcnt[d], 1);
    }
    gbar(2u * nb);

    // Phase R: per-chunk reduction (block b -> one bsum entry); L2-direct loads
    {
        const int* cnt; int* bsum; int n, cb;
        if (b < pblocks) { cnt = g_pcnt; bsum = g_pbsum; n = M_; cb = b; }
        else             { cnt = g_icnt; bsum = g_ibsum; n = N_; cb = b - pblocks; }
        int i = cb * SCAN_B + t;
        sh[t] = (i < n) ? __ldcg(cnt + i) : 0;
        __syncthreads();
        for (int s = SCAN_B / 2; s > 0; s >>= 1) {
            if (t < s) sh[t] += sh[t + s];
            __syncthreads();
        }
        if (t == 0) bsum[cb] = sh[0];
    }
    gbar(3u * nb);

    // Phase S: block 0 exclusive-scans both bsum arrays (each <= SCAN_B entries)
    if (b == 0) {
        for (int which = 0; which < 2; which++) {
            int* bsum = (which == 0) ? g_pbsum : g_ibsum;
            int nbs   = (which == 0) ? pblocks : iblocks;
            int v = (t < nbs) ? __ldcg(bsum + t) : 0;
            sh[t] = v;
            __syncthreads();
            for (int off = 1; off < SCAN_B; off <<= 1) {
                int x = (t >= off) ? sh[t - off] : 0;
                __syncthreads();
                sh[t] += x;
                __syncthreads();
            }
            if (t < nbs) bsum[t] = sh[t] - v;
            __syncthreads();
        }
    }
    gbar(4u * nb);

    // Phase W: per-chunk exclusive scan -> rowptr + cursor; L2-direct loads
    {
        const int* cnt; const int* bsum; int* rowptr; int* cursor; int n, cb;
        if (b < pblocks) {
            cnt = g_pcnt; bsum = g_pbsum; rowptr = g_prow; cursor = g_pcur; n = M_; cb = b;
        } else {
            cnt = g_icnt; bsum = g_ibsum; rowptr = g_irow; cursor = g_icur; n = N_; cb = b - pblocks;
        }
        int i = cb * SCAN_B + t;
        int v = (i < n) ? __ldcg(cnt + i) : 0;
        sh[t] = v;
        __syncthreads();
        for (int off = 1; off < SCAN_B; off <<= 1) {
            int x = (t >= off) ? sh[t - off] : 0;
            __syncthreads();
            sh[t] += x;
            __syncthreads();
        }
        int excl = sh[t] - v + __ldcg(bsum + cb);
        if (i < n) { rowptr[i] = excl; cursor[i] = excl; }
        // R13/R14 BUG WAS HERE: guard must use the LOCAL chunk index so BOTH
        // sides write their sentinel (g_prow[M_]=E and g_irow[N_]=E).
        if (cb == 0 && t == 0) rowptr[n] = E;
    }
    gbar(5u * nb);

    // Phase P: place both CSRs
    for (int e = gt; e < E; e += nthr) {
        int s = g_i32[e];
        int d = g_p32[e];
        g_psrc[atomicAdd(&g_pcur[d], 1)] = s;
        g_isrc[atomicAdd(&g_icur[s], 1)] = d;
    }
}

// ---------------- segmented gather-reduce (EXACT R7: one warp/row, unroll 4) ----------------
__global__ __launch_bounds__(256)
void aggregate_kernel(const float* __restrict__ src, float* __restrict__ dst,
                      const int* __restrict__ row, const int* __restrict__ srcids,
                      int ndst) {
    int w = (int)((blockIdx.x * blockDim.x + threadIdx.x) >> 5);
    if (w >= ndst) return;
    int lane = threadIdx.x & 31;
    int beg = __ldg(row + w);
    int end = __ldg(row + w + 1);
    const float* sp = src + lane * 4;

    float4 a0 = make_float4(0.f, 0.f, 0.f, 0.f);
    float4 a1 = make_float4(0.f, 0.f, 0.f, 0.f);
    float4 a2 = make_float4(0.f, 0.f, 0.f, 0.f);
    float4 a3 = make_float4(0.f, 0.f, 0.f, 0.f);
    int e = beg;
    for (; e + 3 < end; e += 4) {
        int s0 = __ldg(srcids + e),     s1 = __ldg(srcids + e + 1);
        int s2 = __ldg(srcids + e + 2), s3 = __ldg(srcids + e + 3);
        float4 v0 = *(const float4*)(sp + (size_t)s0 * H);
        float4 v1 = *(const float4*)(sp + (size_t)s1 * H);
        float4 v2 = *(const float4*)(sp + (size_t)s2 * H);
        float4 v3 = *(const float4*)(sp + (size_t)s3 * H);
        a0.x += v0.x; a0.y += v0.y; a0.z += v0.z; a0.w += v0.w;
        a1.x += v1.x; a1.y += v1.y; a1.z += v1.z; a1.w += v1.w;
        a2.x += v2.x; a2.y += v2.y; a2.z += v2.z; a2.w += v2.w;
        a3.x += v3.x; a3.y += v3.y; a3.z += v3.z; a3.w += v3.w;
    }
    for (; e < end; e++) {
        float4 v0 = *(const float4*)(sp + (size_t)__ldg(srcids + e) * H);
        a0.x += v0.x; a0.y += v0.y; a0.z += v0.z; a0.w += v0.w;
    }
    a0.x += (a1.x + a2.x) + a3.x;
    a0.y += (a1.y + a2.y) + a3.y;
    a0.z += (a1.z + a2.z) + a3.z;
    a0.w += (a1.w + a2.w) + a3.w;
    *(float4*)(dst + (size_t)w * H + lane * 4) = a0;
}

// ---------------- 3xTF32 GEMM body (R7-proven) ----------------
__device__ __forceinline__ uint32_t to_tf32(float x) {
    uint32_t r;
    asm("cvt.rna.tf32.f32 %0, %1;" : "=r"(r) : "f"(x));
    return r;
}

template<int K, bool FUSED>
__device__ __forceinline__
void tgemm_body(const float* __restrict__ A, const float* __restrict__ W,
                const float* __restrict__ bias, float* __restrict__ C,
                int n, int brow) {
    constexpr int BM = 128, BN = 128, BK = 16;
    __shared__ float As[BM][20];
    __shared__ float BsH[BK][136];
    __shared__ float BsL[BK][136];

    const int tid = threadIdx.x;
    const int wid = tid >> 5, lane = tid & 31;
    const int wr = wid >> 1, wc = wid & 1;
    const int row0 = brow * BM;
    const int l4 = lane >> 2, lm = lane & 3;

    float acc[2][8][4];
#pragma unroll
    for (int mi = 0; mi < 2; mi++)
#pragma unroll
        for (int nj = 0; nj < 8; nj++)
#pragma unroll
            for (int q = 0; q < 4; q++) acc[mi][nj][q] = 0.f;

    for (int k0 = 0; k0 < K; k0 += BK) {
#pragma unroll
        for (int i = 0; i < 2; i++) {
            int f = tid + i * 256;
            int r = f >> 2, c4 = (f & 3) * 4;
            int gr = row0 + r;
            float4 v = make_float4(0.f, 0.f, 0.f, 0.f);
            if (gr < n) v = *(const float4*)(A + (size_t)gr * K + k0 + c4);
            *(float4*)&As[r][c4] = v;
        }
#pragma unroll
        for (int i = 0; i < 2; i++) {
            int f = tid + i * 256;
            int r = f >> 5, c4 = (f & 31) * 4;
            float4 w = *(const float4*)(W + (size_t)(k0 + r) * BN + c4);
            float4 h, lo;
            h.x = __uint_as_float(to_tf32(w.x)); lo.x = w.x - h.x;
            h.y = __uint_as_float(to_tf32(w.y)); lo.y = w.y - h.y;
            h.z = __uint_as_float(to_tf32(w.z)); lo.z = w.z - h.z;
            h.w = __uint_as_float(to_tf32(w.w)); lo.w = w.w - h.w;
            *(float4*)&BsH[r][c4] = h;
            *(float4*)&BsL[r][c4] = lo;
        }
        __syncthreads();

#pragma unroll
        for (int ks = 0; ks < 2; ks++) {
            const int kb = ks * 8 + lm;
            uint32_t ah[2][4], al[2][4];
#pragma unroll
            for (int mi = 0; mi < 2; mi++) {
                int rb = wr * 32 + mi * 16 + l4;
                float av[4];
                av[0] = As[rb][kb];
                av[1] = As[rb + 8][kb];
                av[2] = As[rb][kb + 4];
                av[3] = As[rb + 8][kb + 4];
#pragma unroll
                for (int q = 0; q < 4; q++) {
                    uint32_t hb = to_tf32(av[q]);
                    ah[mi][q] = hb;
                    al[mi][q] = to_tf32(av[q] - __uint_as_float(hb));
                }
            }
#pragma unroll
            for (int nj = 0; nj < 8; nj++) {
                int nn = wc * 64 + nj * 8 + l4;
                uint32_t bh0 = __float_as_uint(BsH[kb][nn]);
                uint32_t bh1 = __float_as_uint(BsH[kb + 4][nn]);
                uint32_t bl0 = __float_as_uint(BsL[kb][nn]);
                uint32_t bl1 = __float_as_uint(BsL[kb + 4][nn]);
#pragma unroll
                for (int mi = 0; mi < 2; mi++) {
                    float* d = acc[mi][nj];
#define TMMA(A0,A1,A2,A3,B0,B1) \
    asm volatile("mma.sync.aligned.m16n8k8.row.col.f32.tf32.tf32.f32 " \
        "{%0,%1,%2,%3},{%4,%5,%6,%7},{%8,%9},{%0,%1,%2,%3};" \
        : "+f"(d[0]), "+f"(d[1]), "+f"(d[2]), "+f"(d[3]) \
        : "r"(A0), "r"(A1), "r"(A2), "r"(A3), "r"(B0), "r"(B1))
                    TMMA(ah[mi][0], ah[mi][1], ah[mi][2], ah[mi][3], bh0, bh1);
                    TMMA(al[mi][0], al[mi][1], al[mi][2], al[mi][3], bh0, bh1);
                    TMMA(ah[mi][0], ah[mi][1], ah[mi][2], ah[mi][3], bl0, bl1);
#undef TMMA
                }
            }
        }
        __syncthreads();
    }

#pragma unroll
    for (int mi = 0; mi < 2; mi++) {
#pragma unroll
        for (int hh = 0; hh < 2; hh++) {
            int r = row0 + wr * 32 + mi * 16 + l4 + hh * 8;
            if (r >= n) continue;
#pragma unroll
            for (int nj = 0; nj < 8; nj++) {
                int cc = wc * 64 + nj * 8 + lm * 2;
                float x0 = fmaxf(acc[mi][nj][hh * 2 + 0] + __ldg(bias + cc), 0.f);
                float x1 = fmaxf(acc[mi][nj][hh * 2 + 1] + __ldg(bias + cc + 1), 0.f);
                if (FUSED) {
                    float2 rv = *(const float2*)(C + (size_t)r * BN + cc);
                    x0 = fmaxf(rv.x + x0, 0.f);
                    x1 = fmaxf(rv.y + x1, 0.f);
                }
                *(float2*)(C + (size_t)r * BN + cc) = make_float2(x0, x1);
            }
        }
    }
}

// round GEMM (fused residual)
__global__ __launch_bounds__(256, 2)
void tgemm_fused_kernel(const float* __restrict__ A, const float* __restrict__ W,
                        const float* __restrict__ bias, float* __restrict__ C, int n) {
    tgemm_body<H, true>(A, W, bias, C, n, blockIdx.x);
}

// both encoders in one launch
__global__ __launch_bounds__(256, 2)
void enc2_kernel(const float* __restrict__ A0, const float* __restrict__ W0,
                 const float* __restrict__ b0, float* __restrict__ C0, int n0, int g0,
                 const float* __restrict__ A1, const float* __restrict__ W1,
                 const float* __restrict__ b1, float* __restrict__ C1, int n1) {
    if ((int)blockIdx.x < g0)
        tgemm_body<DI, false>(A0, W0, b0, C0, n0, blockIdx.x);
    else
        tgemm_body<DI, false>(A1, W1, b1, C1, n1, blockIdx.x - g0);
}

// ---------------- launch ----------------
extern "C" void kernel_launch(void* const* d_in, const int* in_sizes, int n_in,
                              void* d_out, int out_size) {
    const float* item_feat = (const float*)d_in[0];
    const float* pat_feat  = (const float*)d_in[1];
    const void*  iidx_raw  = d_in[2];
    const void*  pidx_raw  = d_in[3];
    const float* W_item = (const float*)d_in[4];
    const float* b_item = (const float*)d_in[5];
    const float* W_pat  = (const float*)d_in[6];
    const float* b_pat  = (const float*)d_in[7];
    const float* W_i2p  = (const float*)d_in[8];
    const float* b_i2p  = (const float*)d_in[9];
    const float* W_p2i  = (const float*)d_in[10];
    const float* b_p2i  = (const float*)d_in[11];

    const int N_ = in_sizes[0] / DI;
    const int M_ = in_sizes[1] / DI;
    const int E_ = in_sizes[2];

    float* h_item = (float*)d_out;
    float* h_pat  = (float*)d_out + (size_t)N_ * H;

    void* p;
    cudaGetSymbolAddress(&p, g_pmsg); float* pmsg = (float*)p;
    cudaGetSymbolAddress(&p, g_imsg); float* imsg = (float*)p;
    cudaGetSymbolAddress(&p, g_psrc); int* psrc = (int*)p;
    cudaGetSymbolAddress(&p, g_isrc); int* isrc = (int*)p;
    cudaGetSymbolAddress(&p, g_prow); int* prow = (int*)p;
    cudaGetSymbolAddress(&p, g_irow); int* irow = (int*)p;

    const int pblocks = (M_ + SCAN_B - 1) / SCAN_B;
    const int iblocks = (N_ + SCAN_B - 1) / SCAN_B;
    const int nb = pblocks + iblocks;           // 138 full-size; <=148 SMs -> co-resident
    const int gN = (N_ + 127) / 128;
    const int gM = (M_ + 127) / 128;

    // idx0: barrier reset
    reset_kernel<<<1, 1>>>();
    // idx1: whole CSR build in one persistent kernel
    csr_kernel<<<nb, SCAN_B>>>(iidx_raw, pidx_raw, E_, M_, N_, pblocks, iblocks, nb);
    // idx2: encoders
    enc2_kernel<<<gN + gM, 256>>>(item_feat, W_item, b_item, h_item, N_, gN,
                                  pat_feat,  W_pat,  b_pat,  h_pat,  M_);

    const int pagg_blocks = (M_ * 32 + 255) / 256;
    const int iagg_blocks = (N_ * 32 + 255) / 256;

    for (int r = 0; r < 2; r++) {
        // idx3 on first iteration -> the profiled slot = p-aggregate
        aggregate_kernel<<<pagg_blocks, 256>>>(h_item, pmsg, prow, psrc, M_);
        tgemm_fused_kernel<<<gM, 256>>>(pmsg, W_i2p, b_i2p, h_pat, M_);
        aggregate_kernel<<<iagg_blocks, 256>>>(h_pat, imsg, irow, isrc, N_);
        tgemm_fused_kernel<<<gN, 256>>>(imsg, W_p2i, b_p2i, h_item, N_);
    }
}

// round 17
// speedup vs baseline: 1.0077x; 1.0077x over previous
#include <cuda_runtime.h>
#include <cstdint>

#define H 128
#define DI 64
#define MAX_N 50000
#define MAX_M 20000
#define MAX_E 1000000
#define SCAN_B 512

// ---------------- scratch (no allocations allowed) — EXACT R7 layout ----------------
__device__ float  g_pmsg[MAX_M * H];
__device__ float  g_imsg[MAX_N * H];
__device__ int    g_i32[MAX_E];
__device__ int    g_p32[MAX_E];
__device__ int    g_psrc[MAX_E];
__device__ int    g_isrc[MAX_E];
__device__ int    g_prow[MAX_M + 1];
__device__ int    g_irow[MAX_N + 1];
__device__ int    g_pcur[MAX_M];
__device__ int    g_icur[MAX_N];
__device__ int    g_pcnt[MAX_M];
__device__ int    g_icnt[MAX_N];
__device__ int    g_pbsum[(MAX_M + SCAN_B - 1) / SCAN_B];
__device__ int    g_ibsum[(MAX_N + SCAN_B - 1) / SCAN_B];

// ---------------- zero both count arrays ----------------
__global__ void zero2_kernel(int N_, int M_) {
    int i = blockIdx.x * blockDim.x + threadIdx.x;
    if (i < N_) g_icnt[i] = 0;
    if (i < M_) g_pcnt[i] = 0;
}

// ---------------- count + narrow (inline int64-vs-int32 detect; R7-proven) ----------------
__global__ void count_kernel(const void* __restrict__ iraw,
                             const void* __restrict__ praw, int E) {
    __shared__ int s_is64;
    int t = threadIdx.x;
    if (t < 32) {
        int nsamp = (E / 2 < 64) ? E / 2 : 64;
        unsigned long long hi = 0;
        for (int i = t; i < nsamp; i += 32)
            hi |= (((const unsigned long long*)iraw)[i] >> 32);
        unsigned any = __ballot_sync(0xFFFFFFFFu, hi != 0ULL);
        if (t == 0) s_is64 = (any == 0u) ? 1 : 0;
    }
    __syncthreads();
    int is64 = s_is64;
    int e = blockIdx.x * blockDim.x + t;
    if (e >= E) return;
    int s = is64 ? (int)((const long long*)iraw)[e] : ((const int*)iraw)[e];
    int d = is64 ? (int)((const long long*)praw)[e] : ((const int*)praw)[e];
    g_i32[e] = s;
    g_p32[e] = d;
    atomicAdd(&g_icnt[s], 1);
    atomicAdd(&g_pcnt[d], 1);
}

__global__ void reduce2_kernel(int pblocks, int M_, int N_) {
    __shared__ int sh[SCAN_B];
    const int* cnt; int* bsum; int n, b;
    if ((int)blockIdx.x < pblocks) { cnt = g_pcnt; bsum = g_pbsum; n = M_; b = blockIdx.x; }
    else { cnt = g_icnt; bsum = g_ibsum; n = N_; b = blockIdx.x - pblocks; }
    int t = threadIdx.x;
    int i = b * SCAN_B + t;
    sh[t] = (i < n) ? cnt[i] : 0;
    __syncthreads();
    for (int s = SCAN_B / 2; s > 0; s >>= 1) {
        if (t < s) sh[t] += sh[t + s];
        __syncthreads();
    }
    if (t == 0) bsum[b] = sh[0];
}

__global__ void scanb2_kernel(int pblocks, int iblocks) {
    __shared__ int sh[1024];
    int* bsum = (blockIdx.x == 0) ? g_pbsum : g_ibsum;
    int nb = (blockIdx.x == 0) ? pblocks : iblocks;
    int t = threadIdx.x;
    int v = (t < nb) ? bsum[t] : 0;
    sh[t] = v;
    __syncthreads();
    for (int off = 1; off < 1024; off <<= 1) {
        int x = (t >= off) ? sh[t - off] : 0;
        __syncthreads();
        sh[t] += x;
        __syncthreads();
    }
    if (t < nb) bsum[t] = sh[t] - v;
}

__global__ void scanc2_kernel(int pblocks, int M_, int N_, int E) {
    __shared__ int sh[SCAN_B];
    const int* cnt; const int* bsum; int* rowptr; int* cursor; int n, b;
    if ((int)blockIdx.x < pblocks) {
        cnt = g_pcnt; bsum = g_pbsum; rowptr = g_prow; cursor = g_pcur; n = M_; b = blockIdx.x;
    } else {
        cnt = g_icnt; bsum = g_ibsum; rowptr = g_irow; cursor = g_icur; n = N_; b = blockIdx.x - pblocks;
    }
    int t = threadIdx.x;
    int i = b * SCAN_B + t;
    int v = (i < n) ? cnt[i] : 0;
    sh[t] = v;
    __syncthreads();
    for (int off = 1; off < SCAN_B; off <<= 1) {
        int x = (t >= off) ? sh[t - off] : 0;
        __syncthreads();
        sh[t] += x;
        __syncthreads();
    }
    int excl = sh[t] - v + bsum[b];
    if (i < n) { rowptr[i] = excl; cursor[i] = excl; }
    if (b == 0 && t == 0) rowptr[n] = E;   // local-b: fires once per side (p at b==0, i at blockIdx.x==pblocks)
}

__global__ void place_kernel(int E) {
    int e = blockIdx.x * blockDim.x + threadIdx.x;
    if (e >= E) return;
    int s = g_i32[e];
    int d = g_p32[e];
    g_psrc[atomicAdd(&g_pcur[d], 1)] = s;
    g_isrc[atomicAdd(&g_icur[s], 1)] = d;
}

// ---------------- segmented gather-reduce: TWO warps per destination row ----------------
// Profile (R16): L2=57%, issue=26%, occ=52% -> latency-bound. Double per-row
// concurrency: warp0 takes [beg,mid), warp1 [mid,end); combine via smem.
__global__ __launch_bounds__(256)
void aggregate_kernel(const float* __restrict__ src, float* __restrict__ dst,
                      const int* __restrict__ row, const int* __restrict__ srcids,
                      int ndst) {
    __shared__ float red[4][H];
    const int pr = threadIdx.x >> 6;           // pair slot in block (0..3)
    const int gpair = blockIdx.x * 4 + pr;     // destination row
    const int half = (threadIdx.x >> 5) & 1;
    const int lane = threadIdx.x & 31;
    const bool valid = gpair < ndst;

    float4 a0 = make_float4(0.f, 0.f, 0.f, 0.f);
    float4 a1 = a0, a2 = a0, a3 = a0;

    if (valid) {
        int beg = __ldg(row + gpair);
        int end = __ldg(row + gpair + 1);
        int mid = (beg + end) >> 1;
        int s0 = half ? mid : beg;
        int s1 = half ? end : mid;
        const float* sp = src + lane * 4;
        int e = s0;
        for (; e + 3 < s1; e += 4) {
            int i0 = __ldg(srcids + e),     i1 = __ldg(srcids + e + 1);
            int i2 = __ldg(srcids + e + 2), i3 = __ldg(srcids + e + 3);
            float4 v0 = *(const float4*)(sp + (size_t)i0 * H);
            float4 v1 = *(const float4*)(sp + (size_t)i1 * H);
            float4 v2 = *(const float4*)(sp + (size_t)i2 * H);
            float4 v3 = *(const float4*)(sp + (size_t)i3 * H);
            a0.x += v0.x; a0.y += v0.y; a0.z += v0.z; a0.w += v0.w;
            a1.x += v1.x; a1.y += v1.y; a1.z += v1.z; a1.w += v1.w;
            a2.x += v2.x; a2.y += v2.y; a2.z += v2.z; a2.w += v2.w;
            a3.x += v3.x; a3.y += v3.y; a3.z += v3.z; a3.w += v3.w;
        }
        for (; e < s1; e++) {
            float4 v0 = *(const float4*)(sp + (size_t)__ldg(srcids + e) * H);
            a0.x += v0.x; a0.y += v0.y; a0.z += v0.z; a0.w += v0.w;
        }
        a0.x += (a1.x + a2.x) + a3.x;
        a0.y += (a1.y + a2.y) + a3.y;
        a0.z += (a1.z + a2.z) + a3.z;
        a0.w += (a1.w + a2.w) + a3.w;
    }

    if (half == 1 && valid)
        *(float4*)&red[pr][lane * 4] = a0;
    __syncthreads();            // all 256 threads reach (no early return)
    if (half == 0 && valid) {
        float4 b = *(const float4*)&red[pr][lane * 4];
        a0.x += b.x; a0.y += b.y; a0.z += b.z; a0.w += b.w;
        *(float4*)(dst + (size_t)gpair * H + lane * 4) = a0;
    }
}

// ---------------- 3xTF32 GEMM body (R7-proven) ----------------
__device__ __forceinline__ uint32_t to_tf32(float x) {
    uint32_t r;
    asm("cvt.rna.tf32.f32 %0, %1;" : "=r"(r) : "f"(x));
    return r;
}

template<int K, bool FUSED>
__device__ __forceinline__
void tgemm_body(const float* __restrict__ A, const float* __restrict__ W,
                const float* __restrict__ bias, float* __restrict__ C,
                int n, int brow) {
    constexpr int BM = 128, BN = 128, BK = 16;
    __shared__ float As[BM][20];
    __shared__ float BsH[BK][136];
    __shared__ float BsL[BK][136];

    const int tid = threadIdx.x;
    const int wid = tid >> 5, lane = tid & 31;
    const int wr = wid >> 1, wc = wid & 1;
    const int row0 = brow * BM;
    const int l4 = lane >> 2, lm = lane & 3;

    float acc[2][8][4];
#pragma unroll
    for (int mi = 0; mi < 2; mi++)
#pragma unroll
        for (int nj = 0; nj < 8; nj++)
#pragma unroll
            for (int q = 0; q < 4; q++) acc[mi][nj][q] = 0.f;

    for (int k0 = 0; k0 < K; k0 += BK) {
#pragma unroll
        for (int i = 0; i < 2; i++) {
            int f = tid + i * 256;
            int r = f >> 2, c4 = (f & 3) * 4;
            int gr = row0 + r;
            float4 v = make_float4(0.f, 0.f, 0.f, 0.f);
            if (gr < n) v = *(const float4*)(A + (size_t)gr * K + k0 + c4);
            *(float4*)&As[r][c4] = v;
        }
#pragma unroll
        for (int i = 0; i < 2; i++) {
            int f = tid + i * 256;
            int r = f >> 5, c4 = (f & 31) * 4;
            float4 w = *(const float4*)(W + (size_t)(k0 + r) * BN + c4);
            float4 h, lo;
            h.x = __uint_as_float(to_tf32(w.x)); lo.x = w.x - h.x;
            h.y = __uint_as_float(to_tf32(w.y)); lo.y = w.y - h.y;
            h.z = __uint_as_float(to_tf32(w.z)); lo.z = w.z - h.z;
            h.w = __uint_as_float(to_tf32(w.w)); lo.w = w.w - h.w;
            *(float4*)&BsH[r][c4] = h;
            *(float4*)&BsL[r][c4] = lo;
        }
        __syncthreads();

#pragma unroll
        for (int ks = 0; ks < 2; ks++) {
            const int kb = ks * 8 + lm;
            uint32_t ah[2][4], al[2][4];
#pragma unroll
            for (int mi = 0; mi < 2; mi++) {
                int rb = wr * 32 + mi * 16 + l4;
                float av[4];
                av[0] = As[rb][kb];
                av[1] = As[rb + 8][kb];
                av[2] = As[rb][kb + 4];
                av[3] = As[rb + 8][kb + 4];
#pragma unroll
                for (int q = 0; q < 4; q++) {
                    uint32_t hb = to_tf32(av[q]);
                    ah[mi][q] = hb;
                    al[mi][q] = to_tf32(av[q] - __uint_as_float(hb));
                }
            }
#pragma unroll
            for (int nj = 0; nj < 8; nj++) {
                int nn = wc * 64 + nj * 8 + l4;
                uint32_t bh0 = __float_as_uint(BsH[kb][nn]);
                uint32_t bh1 = __float_as_uint(BsH[kb + 4][nn]);
                uint32_t bl0 = __float_as_uint(BsL[kb][nn]);
                uint32_t bl1 = __float_as_uint(BsL[kb + 4][nn]);
#pragma unroll
                for (int mi = 0; mi < 2; mi++) {
                    float* d = acc[mi][nj];
#define TMMA(A0,A1,A2,A3,B0,B1) \
    asm volatile("mma.sync.aligned.m16n8k8.row.col.f32.tf32.tf32.f32 " \
        "{%0,%1,%2,%3},{%4,%5,%6,%7},{%8,%9},{%0,%1,%2,%3};" \
        : "+f"(d[0]), "+f"(d[1]), "+f"(d[2]), "+f"(d[3]) \
        : "r"(A0), "r"(A1), "r"(A2), "r"(A3), "r"(B0), "r"(B1))
                    TMMA(ah[mi][0], ah[mi][1], ah[mi][2], ah[mi][3], bh0, bh1);
                    TMMA(al[mi][0], al[mi][1], al[mi][2], al[mi][3], bh0, bh1);
                    TMMA(ah[mi][0], ah[mi][1], ah[mi][2], ah[mi][3], bl0, bl1);
#undef TMMA
                }
            }
        }
        __syncthreads();
    }

#pragma unroll
    for (int mi = 0; mi < 2; mi++) {
#pragma unroll
        for (int hh = 0; hh < 2; hh++) {
            int r = row0 + wr * 32 + mi * 16 + l4 + hh * 8;
            if (r >= n) continue;
#pragma unroll
            for (int nj = 0; nj < 8; nj++) {
                int cc = wc * 64 + nj * 8 + lm * 2;
                float x0 = fmaxf(acc[mi][nj][hh * 2 + 0] + __ldg(bias + cc), 0.f);
                float x1 = fmaxf(acc[mi][nj][hh * 2 + 1] + __ldg(bias + cc + 1), 0.f);
                if (FUSED) {
                    float2 rv = *(const float2*)(C + (size_t)r * BN + cc);
                    x0 = fmaxf(rv.x + x0, 0.f);
                    x1 = fmaxf(rv.y + x1, 0.f);
                }
                *(float2*)(C + (size_t)r * BN + cc) = make_float2(x0, x1);
            }
        }
    }
}

// round GEMM (fused residual)
__global__ __launch_bounds__(256, 2)
void tgemm_fused_kernel(const float* __restrict__ A, const float* __restrict__ W,
                        const float* __restrict__ bias, float* __restrict__ C, int n) {
    tgemm_body<H, true>(A, W, bias, C, n, blockIdx.x);
}

// both encoders in one launch
__global__ __launch_bounds__(256, 2)
void enc2_kernel(const float* __restrict__ A0, const float* __restrict__ W0,
                 const float* __restrict__ b0, float* __restrict__ C0, int n0, int g0,
                 const float* __restrict__ A1, const float* __restrict__ W1,
                 const float* __restrict__ b1, float* __restrict__ C1, int n1) {
    if ((int)blockIdx.x < g0)
        tgemm_body<DI, false>(A0, W0, b0, C0, n0, blockIdx.x);
    else
        tgemm_body<DI, false>(A1, W1, b1, C1, n1, blockIdx.x - g0);
}

// ---------------- launch ----------------
extern "C" void kernel_launch(void* const* d_in, const int* in_sizes, int n_in,
                              void* d_out, int out_size) {
    const float* item_feat = (const float*)d_in[0];
    const float* pat_feat  = (const float*)d_in[1];
    const void*  iidx_raw  = d_in[2];
    const void*  pidx_raw  = d_in[3];
    const float* W_item = (const float*)d_in[4];
    const float* b_item = (const float*)d_in[5];
    const float* W_pat  = (const float*)d_in[6];
    const float* b_pat  = (const float*)d_in[7];
    const float* W_i2p  = (const float*)d_in[8];
    const float* b_i2p  = (const float*)d_in[9];
    const float* W_p2i  = (const float*)d_in[10];
    const float* b_p2i  = (const float*)d_in[11];

    const int N_ = in_sizes[0] / DI;
    const int M_ = in_sizes[1] / DI;
    const int E_ = in_sizes[2];

    float* h_item = (float*)d_out;
    float* h_pat  = (float*)d_out + (size_t)N_ * H;

    void* p;
    cudaGetSymbolAddress(&p, g_pmsg); float* pmsg = (float*)p;
    cudaGetSymbolAddress(&p, g_imsg); float* imsg = (float*)p;
    cudaGetSymbolAddress(&p, g_psrc); int* psrc = (int*)p;
    cudaGetSymbolAddress(&p, g_isrc); int* isrc = (int*)p;
    cudaGetSymbolAddress(&p, g_prow); int* prow = (int*)p;
    cudaGetSymbolAddress(&p, g_irow); int* irow = (int*)p;

    const int pblocks = (M_ + SCAN_B - 1) / SCAN_B;
    const int iblocks = (N_ + SCAN_B - 1) / SCAN_B;
    const int maxnm = (N_ > M_) ? N_ : M_;

    // ---- CSR build (R7-proven sequence) ----
    zero2_kernel<<<(maxnm + 255) / 256, 256>>>(N_, M_);
    count_kernel<<<(E_ + 255) / 256, 256>>>(iidx_raw, pidx_raw, E_);
    reduce2_kernel<<<pblocks + iblocks, SCAN_B>>>(pblocks, M_, N_);
    scanb2_kernel<<<2, 1024>>>(pblocks, iblocks);
    scanc2_kernel<<<pblocks + iblocks, SCAN_B>>>(pblocks, M_, N_, E_);
    place_kernel<<<(E_ + 255) / 256, 256>>>(E_);

    // ---- encoders (one launch, K=64 both) ----
    const int gN = (N_ + 127) / 128;
    const int gM = (M_ + 127) / 128;
    enc2_kernel<<<gN + gM, 256>>>(item_feat, W_item, b_item, h_item, N_, gN,
                                  pat_feat,  W_pat,  b_pat,  h_pat,  M_);

    // 2 warps (64 threads) per destination row -> 4 rows per 256-thread block
    const int pagg_blocks = (M_ + 3) / 4;
    const int iagg_blocks = (N_ + 3) / 4;

    for (int r = 0; r < 2; r++) {
        aggregate_kernel<<<pagg_blocks, 256>>>(h_item, pmsg, prow, psrc, M_);
        tgemm_fused_kernel<<<gM, 256>>>(pmsg, W_i2p, b_i2p, h_pat, M_);
        aggregate_kernel<<<iagg_blocks, 256>>>(h_pat, imsg, irow, isrc, N_);
        tgemm_fused_kernel<<<gN, 256>>>(imsg, W_p2i, b_p2i, h_item, N_);
    }
}